// round 10
// baseline (speedup 1.0000x reference)
#include <cuda_runtime.h>
#include <stdint.h>

// CornerActivationB: out[b, g*16+d] = bilinear interp of params[g, 0..3, d]
//   u_i = (clip(x_i,-1,1)+1)*0.5
//   out = (1-u0)(1-u1)P0 + (1-u0)u1 P1 + u0(1-u1)P2 + u0 u1 P3
//
// BATCH=8192, GROUPS=512, OUT_DIM=16.
// X: [8192,1024] f32, params: [512,4,16] f32, out: [8192,8192] f32.
//
// R10: instruction-density experiment. Each thread owns (group, d-HALF):
// 8 output floats/row (2x R6). Coefficient math (~10 ops) amortizes over
// 32 FMAs instead of 16; LDG broadcast 4-way -> 2-way. ~2x fewer issued
// instructions per stored byte. Params: 8 float4 = 32 regs/thread ->
// launch_bounds(256,4). Single wave: 592 blocks = 148 SMs * 4.
// Per warp per row: 1024B via two STG.128 (complementary 16B offsets,
// L2-merged). Contiguous 4-row btiles for DRAM locality (R6/R7 lesson).

#define GROUPS    512
#define OUT_DIM   16
#define BATCH     8192
#define GDIM      (GROUPS * OUT_DIM)   // 8192
#define XDIM      (GROUPS * 2)         // 1024
#define G_TILE    128                  // groups per block (256 thr / 2 halves)
#define NGT       (GROUPS / G_TILE)    // 4 gtiles
#define B_TILE    4
#define NBT       (BATCH / B_TILE)     // 2048
#define NCHUNK    148                  // 4*148 = 592 = 148 SMs * 4 -> one wave

__global__ void __launch_bounds__(256, 4)
corner_act_kernel(const float* __restrict__ X,
                  const float* __restrict__ P,
                  float* __restrict__ out)
{
    const int tid   = threadIdx.x;
    const int h     = tid & 1;            // d-half: d in [8h, 8h+8)
    const int gl    = tid >> 1;           // group within tile (0..127)
    const int gtile = blockIdx.x & (NGT - 1);   // 0..3
    const int chunk = blockIdx.x >> 2;          // 0..147
    const int g     = gtile * G_TILE + gl;

    // params[g, j, d]: float4 index g*16 + j*4 + h*2 + {0,1}  (32 regs)
    const float4* Pg = reinterpret_cast<const float4*>(P) + (size_t)g * 16 + h * 2;
    const float4 p00 = Pg[0],  p01 = Pg[1];    // j=0
    const float4 p10 = Pg[4],  p11 = Pg[5];    // j=1
    const float4 p20 = Pg[8],  p21 = Pg[9];    // j=2
    const float4 p30 = Pg[12], p31 = Pg[13];   // j=3

    const float2* X2 = reinterpret_cast<const float2*>(X) + g;     // + b*(XDIM/2)
    float*        O  = out + (size_t)g * OUT_DIM + h * 8;          // + b*GDIM

    for (int bt = chunk; bt < NBT; bt += NCHUNK) {
        const int b0 = bt * B_TILE;

        #pragma unroll
        for (int r = 0; r < B_TILE; ++r) {
            const int b = b0 + r;
            float2 xv = __ldg(X2 + (size_t)b * (XDIM / 2));  // 2-way broadcast
            float u0 = (fminf(fmaxf(xv.x, -1.0f), 1.0f) + 1.0f) * 0.5f;
            float u1 = (fminf(fmaxf(xv.y, -1.0f), 1.0f) + 1.0f) * 0.5f;
            float v0 = 1.0f - u0;
            float v1 = 1.0f - u1;
            float c00 = v0 * v1;
            float c01 = v0 * u1;
            float c10 = u0 * v1;
            float c11 = u0 * u1;

            float4 oa, ob;
            oa.x = c00 * p00.x + c01 * p10.x + c10 * p20.x + c11 * p30.x;
            oa.y = c00 * p00.y + c01 * p10.y + c10 * p20.y + c11 * p30.y;
            oa.z = c00 * p00.z + c01 * p10.z + c10 * p20.z + c11 * p30.z;
            oa.w = c00 * p00.w + c01 * p10.w + c10 * p20.w + c11 * p30.w;
            ob.x = c00 * p01.x + c01 * p11.x + c10 * p21.x + c11 * p31.x;
            ob.y = c00 * p01.y + c01 * p11.y + c10 * p21.y + c11 * p31.y;
            ob.z = c00 * p01.z + c01 * p11.z + c10 * p21.z + c11 * p31.z;
            ob.w = c00 * p01.w + c01 * p11.w + c10 * p21.w + c11 * p31.w;

            float4* dst = reinterpret_cast<float4*>(O + (size_t)b * GDIM);
            dst[0] = oa;
            dst[1] = ob;
        }
    }
}

extern "C" void kernel_launch(void* const* d_in, const int* in_sizes, int n_in,
                              void* d_out, int out_size)
{
    const float* X = (const float*)d_in[0];
    const float* P = (const float*)d_in[1];
    float* out = (float*)d_out;

    dim3 grid(NGT * NCHUNK);   // 592 blocks = one wave at 4 blocks/SM
    dim3 block(256);
    corner_act_kernel<<<grid, block>>>(X, P, out);
}

// round 11
// speedup vs baseline: 1.5229x; 1.5229x over previous
#include <cuda_runtime.h>
#include <stdint.h>

// CornerActivationB: out[b, g*16+d] = bilinear interp of params[g, 0..3, d]
//   u_i = (clip(x_i,-1,1)+1)*0.5
//   out = (1-u0)(1-u1)P0 + (1-u0)u1 P1 + u0(1-u1)P2 + u0 u1 P3
//
// BATCH=8192, GROUPS=512, OUT_DIM=16.
// X: [8192,1024] f32, params: [512,4,16] f32, out: [8192,8192] f32.
//
// FINAL (== R6, session best: 49.4us kernel / 55.8us total).
// Session conclusions baked into this config:
//  - Kernel is bound by the HBM3e write-stream ceiling: 256MB fp32 output at
//    ~5.2 TB/s (~62% of 8TB/s spec). Occ 44-68%, STG.64/128, wave structure,
//    load batching, cache hints, and instruction density all failed to move it.
//  - Winning ingredients: persistent single wave (736 blocks = 148 SMs x 5),
//    B_TILE=4 CONTIGUOUS batch rows per step (DRAM row locality; scattered
//    rows cost ~4%), params register-resident per block (zero steady-state
//    param traffic), 512B-per-warp contiguous STG.128 stores, plain LDG
//    (streaming/evict-first hints regressed 65%).

#define GROUPS    512
#define OUT_DIM   16
#define BATCH     8192
#define GDIM      (GROUPS * OUT_DIM)   // 8192
#define XDIM      (GROUPS * 2)         // 1024
#define G_TILE    64
#define B_TILE    4
#define NBT       (BATCH / B_TILE)     // 2048 btiles per gtile
#define NCHUNK    92                   // blocks per gtile; 8*92=736 = one wave @5/SM

__global__ void __launch_bounds__(256, 5)
corner_act_kernel(const float* __restrict__ X,
                  const float* __restrict__ P,
                  float* __restrict__ out)
{
    const int tid   = threadIdx.x;
    const int q     = tid & 3;           // d-quad (0..3)
    const int gl    = tid >> 2;          // group within tile (0..63)
    const int gtile = blockIdx.x & 7;    // 0..7
    const int chunk = blockIdx.x >> 3;   // 0..91
    const int g     = gtile * G_TILE + gl;

    // params[g, j, d]: float4 index g*16 + j*4 + q  (loaded once per block)
    const float4* Pg = reinterpret_cast<const float4*>(P) + (size_t)g * 16;
    const float4 p0 = Pg[0 * 4 + q];
    const float4 p1 = Pg[1 * 4 + q];
    const float4 p2 = Pg[2 * 4 + q];
    const float4 p3 = Pg[3 * 4 + q];

    const float2* X2 = reinterpret_cast<const float2*>(X) + g;   // + b*(XDIM/2)
    float*        O  = out + (size_t)g * OUT_DIM + q * 4;        // + b*GDIM

    for (int bt = chunk; bt < NBT; bt += NCHUNK) {
        const int b0 = bt * B_TILE;
        const float2* Xp = X2 + (size_t)b0 * (XDIM / 2);
        float*        Op = O  + (size_t)b0 * GDIM;

        #pragma unroll
        for (int r = 0; r < B_TILE; ++r) {
            float2 xv = __ldg(Xp + (size_t)r * (XDIM / 2));  // 4-way broadcast
            float u0 = (fminf(fmaxf(xv.x, -1.0f), 1.0f) + 1.0f) * 0.5f;
            float u1 = (fminf(fmaxf(xv.y, -1.0f), 1.0f) + 1.0f) * 0.5f;
            float v0 = 1.0f - u0;
            float v1 = 1.0f - u1;
            float c00 = v0 * v1;
            float c01 = v0 * u1;
            float c10 = u0 * v1;
            float c11 = u0 * u1;

            float4 o;
            o.x = c00 * p0.x + c01 * p1.x + c10 * p2.x + c11 * p3.x;
            o.y = c00 * p0.y + c01 * p1.y + c10 * p2.y + c11 * p3.y;
            o.z = c00 * p0.z + c01 * p1.z + c10 * p2.z + c11 * p3.z;
            o.w = c00 * p0.w + c01 * p1.w + c10 * p2.w + c11 * p3.w;

            *reinterpret_cast<float4*>(Op + (size_t)r * GDIM) = o;
        }
    }
}

extern "C" void kernel_launch(void* const* d_in, const int* in_sizes, int n_in,
                              void* d_out, int out_size)
{
    const float* X = (const float*)d_in[0];
    const float* P = (const float*)d_in[1];
    float* out = (float*)d_out;

    dim3 grid(8 * NCHUNK);   // 736 blocks = one wave at 5 blocks/SM
    dim3 block(256);
    corner_act_kernel<<<grid, block>>>(X, P, out);
}